// round 13
// baseline (speedup 1.0000x reference)
#include <cuda_runtime.h>
#include <cuda_bf16.h>
#include <cstdint>

#define MAX_NODES 100000
#define MAX_EDGES 625000
#define F 128
#define SSTRIDE 136   // padded bf16 row stride -> conflict-free fragment LDS
#define SCAN_B 512    // nodes per scan chunk
#define GTILE 128     // rows per tile (persistent gemm loop)

__device__ __align__(16) float g_agg[(size_t)MAX_NODES * F];
__device__ int g_cnt[MAX_NODES];        // zero-init at load; re-zeroed each run
__device__ int g_base[MAX_NODES];
__device__ int g_cursor[MAX_NODES];
__device__ int g_sorted[MAX_EDGES];
__device__ int g_bsums[256];
__device__ int g_ticket;
__device__ unsigned g_barArr;           // grid barrier state (zero-init)
__device__ volatile unsigned g_barGen;  // generation counter (monotonic)
// pre-split weight planes (hi/lo bf16)
__device__ __align__(16) __nv_bfloat16 g_whi[F * F];
__device__ __align__(16) __nv_bfloat16 g_wlo[F * F];
__device__ __align__(16) __nv_bfloat16 g_bhi[F * F];
__device__ __align__(16) __nv_bfloat16 g_blo[F * F];

// ---------------------------------------------------------------------------
// Grid-wide barrier (all CTAs co-resident; ncta derived from occupancy API).
// ---------------------------------------------------------------------------
__device__ __forceinline__ void gsync(int ncta) {
    __syncthreads();
    if (threadIdx.x == 0) {
        __threadfence();
        unsigned gen = g_barGen;
        if (atomicAdd(&g_barArr, 1u) == (unsigned)ncta - 1u) {
            g_barArr = 0u;
            __threadfence();
            g_barGen = gen + 1u;
        } else {
            while (g_barGen == gen) { }
        }
    }
    __syncthreads();
}

// Inclusive block scan over 512 threads (16 warps) via shuffles.
__device__ __forceinline__ int block_scan_incl(int v, int* wsum) {
    int tid = threadIdx.x, lane = tid & 31, wid = tid >> 5;
    int s = v;
#pragma unroll
    for (int off = 1; off < 32; off <<= 1) {
        int t = __shfl_up_sync(0xffffffffu, s, off);
        if (lane >= off) s += t;
    }
    if (lane == 31) wsum[wid] = s;
    __syncthreads();
    if (wid == 0 && lane < 16) {
        int w = wsum[lane];
#pragma unroll
        for (int off = 1; off < 16; off <<= 1) {
            int t = __shfl_up_sync(0x0000ffffu, w, off);
            if (lane >= off) w += t;
        }
        wsum[lane] = w;
    }
    __syncthreads();
    return s + ((wid > 0) ? wsum[wid - 1] : 0);
}

// ---------------------------------------------------------------------------
// PREP: one persistent kernel = weight split + hist + scan + offsets + bucket
// ---------------------------------------------------------------------------
__global__ __launch_bounds__(512, 2) void prep_all(
        const float* __restrict__ W, const float* __restrict__ B,
        const int* __restrict__ ei, int N, int E, int nb, int ncta) {
    __shared__ int wsum[16];
    __shared__ int sc[SCAN_B];
    const int tid = threadIdx.x;
    const int gid = blockIdx.x * 512 + tid;
    const int stride = ncta * 512;

    // -- Phase A: ticket reset, weight hi/lo split, src histogram --
    if (gid == 0) g_ticket = 0;
    for (int i = gid; i < F * F; i += stride) {
        float w = W[i];
        __nv_bfloat16 h = __float2bfloat16(w);
        g_whi[i] = h;
        g_wlo[i] = __float2bfloat16(w - __bfloat162float(h));
        float b = B[i];
        h = __float2bfloat16(b);
        g_bhi[i] = h;
        g_blo[i] = __float2bfloat16(b - __bfloat162float(h));
    }
    for (int e = gid; e < E; e += stride)
        atomicAdd(&g_cnt[ei[e]], 1);
    gsync(ncta);

    // -- Phase B: per-chunk exclusive scans, emit chunk sums --
    for (int c = blockIdx.x; c < nb; c += ncta) {
        int i = c * SCAN_B + tid;
        int v = (i < N) ? g_cnt[i] : 0;
        int incl = block_scan_incl(v, wsum);
        if (i < N) g_base[i] = incl - v;
        if (tid == SCAN_B - 1) g_bsums[c] = incl;
        __syncthreads();   // wsum reuse
    }
    gsync(ncta);

    // -- Phase C: chunk-sum prefix (redundant per CTA), apply offsets,
    //    seed cursors, re-zero cnt for next replay --
    {
        int v = (tid < nb) ? g_bsums[tid] : 0;
        int incl = block_scan_incl(v, wsum);
        sc[tid] = incl;
        __syncthreads();
        for (int c = blockIdx.x; c < nb; c += ncta) {
            int offset = (c > 0) ? sc[c - 1] : 0;
            int i = c * SCAN_B + tid;
            if (i < N) {
                int val = g_base[i] + offset;
                g_base[i] = val;
                g_cursor[i] = val;
                g_cnt[i] = 0;
            }
        }
    }
    gsync(ncta);

    // -- Phase D: bucket dst indices into CSR order --
    for (int e = gid; e < E; e += stride) {
        int src = ei[e];
        int dst = ei[E + e];
        int pos = atomicAdd(&g_cursor[src], 1);
        g_sorted[pos] = dst;
    }
}

// ---------------------------------------------------------------------------
// P7: gather-aggregate. One warp per node, 4-way unrolled gather for MLP.
// (Standalone at high occupancy — round-10 lesson: do NOT fuse.)
// ---------------------------------------------------------------------------
__global__ __launch_bounds__(256) void p7_gather(
        const float* __restrict__ x, int N, int E) {
    int n = (blockIdx.x * 256 + threadIdx.x) >> 5;
    int lane = threadIdx.x & 31;
    if (n >= N) return;
    int s = g_base[n];
    int eend = (n + 1 < N) ? g_base[n + 1] : E;
    int cnt = eend - s;
    const float4* x4 = reinterpret_cast<const float4*>(x);
    const int* sp = g_sorted + s;
    float4 acc = make_float4(0.f, 0.f, 0.f, 0.f);
    for (int b = 0; b < cnt; b += 32) {
        int dv = (b + lane < cnt) ? sp[b + lane] : 0;
        int m = min(32, cnt - b);
        int j = 0;
        for (; j + 4 <= m; j += 4) {
            int d0 = __shfl_sync(0xffffffffu, dv, j);
            int d1 = __shfl_sync(0xffffffffu, dv, j + 1);
            int d2 = __shfl_sync(0xffffffffu, dv, j + 2);
            int d3 = __shfl_sync(0xffffffffu, dv, j + 3);
            float4 v0 = x4[(size_t)d0 * 32 + lane];
            float4 v1 = x4[(size_t)d1 * 32 + lane];
            float4 v2 = x4[(size_t)d2 * 32 + lane];
            float4 v3 = x4[(size_t)d3 * 32 + lane];
            acc.x += v0.x; acc.y += v0.y; acc.z += v0.z; acc.w += v0.w;
            acc.x += v1.x; acc.y += v1.y; acc.z += v1.z; acc.w += v1.w;
            acc.x += v2.x; acc.y += v2.y; acc.z += v2.z; acc.w += v2.w;
            acc.x += v3.x; acc.y += v3.y; acc.z += v3.z; acc.w += v3.w;
        }
        for (; j < m; j++) {
            int d = __shfl_sync(0xffffffffu, dv, j);
            float4 v = x4[(size_t)d * 32 + lane];
            acc.x += v.x; acc.y += v.y; acc.z += v.z; acc.w += v.w;
        }
    }
    float rd = (cnt > 0) ? (1.0f / (float)cnt) : 1.0f;
    acc.x *= rd; acc.y *= rd; acc.z *= rd; acc.w *= rd;
    reinterpret_cast<float4*>(g_agg + (size_t)n * F)[lane] = acc;
}

// ---------------------------------------------------------------------------
// K2: PERSISTENT fused GEMM  out = agg @ W^T + x @ B^T  (bf16x3 mma.sync).
// Weights staged once per CTA; dynamic tile ticket; x-tile register prefetch.
// ---------------------------------------------------------------------------
__device__ __forceinline__ void bsplit(float v, __nv_bfloat16* hi, __nv_bfloat16* lo) {
    __nv_bfloat16 h = __float2bfloat16(v);
    *hi = h;
    *lo = __float2bfloat16(v - __bfloat162float(h));
}

#define MMA_BF16(d, a, b)                                                     \
    asm volatile("mma.sync.aligned.m16n8k16.row.col.f32.bf16.bf16.f32 "       \
                 "{%0,%1,%2,%3}, {%4,%5,%6,%7}, {%8,%9}, {%0,%1,%2,%3};"      \
                 : "+f"((d)[0]), "+f"((d)[1]), "+f"((d)[2]), "+f"((d)[3])     \
                 : "r"((a)[0]), "r"((a)[1]), "r"((a)[2]), "r"((a)[3]),        \
                   "r"((b)[0]), "r"((b)[1]))

__device__ __forceinline__ void mma_phase(
        const __nv_bfloat16* __restrict__ wh, const __nv_bfloat16* __restrict__ wl,
        const __nv_bfloat16* __restrict__ sAhi, const __nv_bfloat16* __restrict__ sAlo,
        int wm, int wn, int g, int tg, float (&acc)[2][8][4]) {
#pragma unroll
    for (int ks = 0; ks < 8; ks++) {
        const int kc = ks * 16 + tg * 2;
        uint32_t bhi[8][2], blo[8][2];
#pragma unroll
        for (int nt = 0; nt < 8; nt++) {
            int j0 = wn * 64 + nt * 8 + g;
            const __nv_bfloat16* p = wh + j0 * SSTRIDE + kc;
            bhi[nt][0] = *reinterpret_cast<const uint32_t*>(p);
            bhi[nt][1] = *reinterpret_cast<const uint32_t*>(p + 8);
            const __nv_bfloat16* q = wl + j0 * SSTRIDE + kc;
            blo[nt][0] = *reinterpret_cast<const uint32_t*>(q);
            blo[nt][1] = *reinterpret_cast<const uint32_t*>(q + 8);
        }
#pragma unroll
        for (int mt = 0; mt < 2; mt++) {
            int r0 = wm * 32 + mt * 16 + g;
            uint32_t ahi[4], alo[4];
            const __nv_bfloat16* p0 = sAhi + r0 * SSTRIDE + kc;
            const __nv_bfloat16* p1 = sAhi + (r0 + 8) * SSTRIDE + kc;
            ahi[0] = *reinterpret_cast<const uint32_t*>(p0);
            ahi[1] = *reinterpret_cast<const uint32_t*>(p1);
            ahi[2] = *reinterpret_cast<const uint32_t*>(p0 + 8);
            ahi[3] = *reinterpret_cast<const uint32_t*>(p1 + 8);
            const __nv_bfloat16* q0 = sAlo + r0 * SSTRIDE + kc;
            const __nv_bfloat16* q1 = sAlo + (r0 + 8) * SSTRIDE + kc;
            alo[0] = *reinterpret_cast<const uint32_t*>(q0);
            alo[1] = *reinterpret_cast<const uint32_t*>(q1);
            alo[2] = *reinterpret_cast<const uint32_t*>(q0 + 8);
            alo[3] = *reinterpret_cast<const uint32_t*>(q1 + 8);
#pragma unroll
            for (int nt = 0; nt < 8; nt++) {
                MMA_BF16(acc[mt][nt], ahi, bhi[nt]);
                MMA_BF16(acc[mt][nt], ahi, blo[nt]);
                MMA_BF16(acc[mt][nt], alo, bhi[nt]);
            }
        }
    }
}

__global__ __launch_bounds__(256, 1) void gemm_persist(
        const float* __restrict__ x, float* __restrict__ out,
        int N, int ntiles) {
    extern __shared__ __nv_bfloat16 smem[];
    __nv_bfloat16* sWhi = smem;
    __nv_bfloat16* sWlo = sWhi + 128 * SSTRIDE;
    __nv_bfloat16* sBhi = sWlo + 128 * SSTRIDE;
    __nv_bfloat16* sBlo = sBhi + 128 * SSTRIDE;
    __nv_bfloat16* sAhi = sBlo + 128 * SSTRIDE;   // A tile (reused per phase)
    __nv_bfloat16* sAlo = sAhi + 128 * SSTRIDE;
    __shared__ int s_tile;

    const int tid = threadIdx.x;
    const int lane = tid & 31;
    const int warp = tid >> 5;
    const int wm = warp & 3;
    const int wn = warp >> 2;
    const int g = lane >> 2;
    const int tg = lane & 3;
    const float4* x4 = reinterpret_cast<const float4*>(x);

    // Stage all 4 weight planes ONCE per CTA.
#pragma unroll 4
    for (int i = tid; i < 128 * 16; i += 256) {
        int r = i >> 4;
        int c8 = (i & 15) << 3;
        *reinterpret_cast<uint4*>(sWhi + r * SSTRIDE + c8) =
            reinterpret_cast<const uint4*>(g_whi)[i];
        *reinterpret_cast<uint4*>(sWlo + r * SSTRIDE + c8) =
            reinterpret_cast<const uint4*>(g_wlo)[i];
        *reinterpret_cast<uint4*>(sBhi + r * SSTRIDE + c8) =
            reinterpret_cast<const uint4*>(g_bhi)[i];
        *reinterpret_cast<uint4*>(sBlo + r * SSTRIDE + c8) =
            reinterpret_cast<const uint4*>(g_blo)[i];
    }

    while (true) {
        __syncthreads();
        if (tid == 0) s_tile = atomicAdd(&g_ticket, 1);
        __syncthreads();
        int tile = s_tile;
        if (tile >= ntiles) break;
        int rowBase = tile * GTILE;

        float acc[2][8][4];
#pragma unroll
        for (int a = 0; a < 2; a++)
#pragma unroll
            for (int b = 0; b < 8; b++)
#pragma unroll
                for (int c = 0; c < 4; c++) acc[a][b][c] = 0.f;

        // ---- stage agg tile (phase 0 A) ----
#pragma unroll 4
        for (int i = tid; i < GTILE * 32; i += 256) {
            int r = i >> 5;
            int c4 = (i & 31) << 2;
            int gr = rowBase + r;
            float4 v = make_float4(0.f, 0.f, 0.f, 0.f);
            if (gr < N)
                v = reinterpret_cast<const float4*>(g_agg)[(size_t)gr * 32 + (i & 31)];
            int o = r * SSTRIDE + c4;
            bsplit(v.x, sAhi + o, sAlo + o);
            bsplit(v.y, sAhi + o + 1, sAlo + o + 1);
            bsplit(v.z, sAhi + o + 2, sAlo + o + 2);
            bsplit(v.w, sAhi + o + 3, sAlo + o + 3);
        }
        // ---- prefetch x tile into registers (hides under phase-0 MMA) ----
        float4 xr[16];
#pragma unroll
        for (int j = 0; j < 16; j++) {
            int i = tid + j * 256;
            int gr = rowBase + (i >> 5);
            xr[j] = (gr < N) ? x4[(size_t)gr * 32 + (i & 31)]
                             : make_float4(0.f, 0.f, 0.f, 0.f);
        }
        __syncthreads();

        mma_phase(sWhi, sWlo, sAhi, sAlo, wm, wn, g, tg, acc);   // phase 0

        __syncthreads();   // phase-0 fragment reads done before restage
#pragma unroll
        for (int j = 0; j < 16; j++) {
            int i = tid + j * 256;
            int o = (i >> 5) * SSTRIDE + ((i & 31) << 2);
            bsplit(xr[j].x, sAhi + o, sAlo + o);
            bsplit(xr[j].y, sAhi + o + 1, sAlo + o + 1);
            bsplit(xr[j].z, sAhi + o + 2, sAlo + o + 2);
            bsplit(xr[j].w, sAhi + o + 3, sAlo + o + 3);
        }
        __syncthreads();

        mma_phase(sBhi, sBlo, sAhi, sAlo, wm, wn, g, tg, acc);   // phase 1

        // Epilogue
#pragma unroll
        for (int mt = 0; mt < 2; mt++) {
            int r = rowBase + wm * 32 + mt * 16 + g;
#pragma unroll
            for (int nt = 0; nt < 8; nt++) {
                int c = wn * 64 + nt * 8 + tg * 2;
                if (r < N) {
                    float2 v = make_float2(acc[mt][nt][0], acc[mt][nt][1]);
                    *reinterpret_cast<float2*>(out + (size_t)r * F + c) = v;
                }
                if (r + 8 < N) {
                    float2 v = make_float2(acc[mt][nt][2], acc[mt][nt][3]);
                    *reinterpret_cast<float2*>(out + (size_t)(r + 8) * F + c) = v;
                }
            }
        }
    }
}

// ---------------------------------------------------------------------------
extern "C" void kernel_launch(void* const* d_in, const int* in_sizes, int n_in,
                              void* d_out, int out_size) {
    const float* x = (const float*)d_in[0];
    const int* ei = (const int*)d_in[1];     // int32 (JAX x64-disabled)
    const float* W = (const float*)d_in[2];
    const float* B = (const float*)d_in[3];
    float* out = (float*)d_out;

    int N = in_sizes[0] / F;   // 100000
    int E = in_sizes[1] / 2;   // 625000
    if (N > MAX_NODES) N = MAX_NODES;
    if (E > MAX_EDGES) E = MAX_EDGES;

    int nb = (N + SCAN_B - 1) / SCAN_B;      // scan chunks (196)

    // co-residency-safe CTA count for the grid-synced prep kernel
    int dev = 0, sms = 148, bpm = 0;
    cudaGetDevice(&dev);
    cudaDeviceGetAttribute(&sms, cudaDevAttrMultiProcessorCount, dev);
    cudaOccupancyMaxActiveBlocksPerMultiprocessor(&bpm, prep_all, 512, 0);
    if (bpm < 1) bpm = 1;
    int ncta = sms * bpm;
    if (ncta > 1024) ncta = 1024;

    prep_all<<<ncta, 512>>>(W, B, ei, N, E, nb, ncta);
    p7_gather<<<(N * 32 + 255) / 256, 256>>>(x, N, E);

    // smem: 6 planes * 128 rows * SSTRIDE bf16 = 208896 B
    size_t smem = (size_t)6 * 128 * SSTRIDE * sizeof(__nv_bfloat16);
    cudaFuncSetAttribute(gemm_persist, cudaFuncAttributeMaxDynamicSharedMemorySize,
                         (int)smem);
    int ntiles = (N + GTILE - 1) / GTILE;
    gemm_persist<<<152, 256, smem>>>(x, out, N, ntiles);
}

// round 14
// speedup vs baseline: 1.0469x; 1.0469x over previous
#include <cuda_runtime.h>
#include <cuda_bf16.h>
#include <cstdint>

#define MAX_NODES 100000
#define MAX_EDGES 625000
#define F 128
#define SSTRIDE 136   // padded bf16 row stride -> conflict-free fragment LDS
#define SCAN_B 512    // nodes per scan block
#define GTILE 128     // rows per tile

__device__ int g_cnt[MAX_NODES];        // zero-init at load; re-zeroed by p45
__device__ int g_base[MAX_NODES];
__device__ int g_cursor[MAX_NODES];
__device__ int g_sorted[MAX_EDGES];
__device__ int g_bsums[256];
// aggregated features, pre-split bf16 hi/lo planes (written by p7)
__device__ __align__(16) __nv_bfloat16 g_ahi[(size_t)MAX_NODES * F];
__device__ __align__(16) __nv_bfloat16 g_alo[(size_t)MAX_NODES * F];
// pre-split weight planes (hi/lo bf16), filled once per launch
__device__ __align__(16) __nv_bfloat16 g_whi[F * F];
__device__ __align__(16) __nv_bfloat16 g_wlo[F * F];
__device__ __align__(16) __nv_bfloat16 g_bhi[F * F];
__device__ __align__(16) __nv_bfloat16 g_blo[F * F];

// ---------------------------------------------------------------------------
// P1: pre-split W/B into bf16 hi/lo planes
// ---------------------------------------------------------------------------
__global__ void p1_conv(const float* __restrict__ W, const float* __restrict__ B) {
    int i = blockIdx.x * blockDim.x + threadIdx.x;
    float w = W[i];
    __nv_bfloat16 h = __float2bfloat16(w);
    g_whi[i] = h;
    g_wlo[i] = __float2bfloat16(w - __bfloat162float(h));
    float b = B[i];
    h = __float2bfloat16(b);
    g_bhi[i] = h;
    g_blo[i] = __float2bfloat16(b - __bfloat162float(h));
}

// P2: histogram of src
__global__ void p2_hist(const int* __restrict__ ei, int E) {
    int e = blockIdx.x * blockDim.x + threadIdx.x;
    if (e < E) atomicAdd(&g_cnt[ei[e]], 1);
}

// P3: per-block exclusive scan via warp shuffles (512 threads, 16 warps)
__global__ __launch_bounds__(SCAN_B) void p3_scan(int N) {
    __shared__ int wsum[16];
    int tid = threadIdx.x;
    int lane = tid & 31;
    int wid = tid >> 5;
    int i = blockIdx.x * SCAN_B + tid;
    int v = (i < N) ? g_cnt[i] : 0;
    int s = v;
#pragma unroll
    for (int off = 1; off < 32; off <<= 1) {
        int t = __shfl_up_sync(0xffffffffu, s, off);
        if (lane >= off) s += t;
    }
    if (lane == 31) wsum[wid] = s;
    __syncthreads();
    if (wid == 0 && lane < 16) {
        int w = wsum[lane];
#pragma unroll
        for (int off = 1; off < 16; off <<= 1) {
            int t = __shfl_up_sync(0x0000ffffu, w, off);
            if (lane >= off) w += t;
        }
        wsum[lane] = w;
    }
    __syncthreads();
    int incl = s + ((wid > 0) ? wsum[wid - 1] : 0);
    if (i < N) g_base[i] = incl - v;            // exclusive within block
    if (tid == SCAN_B - 1) g_bsums[blockIdx.x] = incl;
}

// P45: redundant block-sum scan per block, apply offset, seed cursors,
// re-zero g_cnt for next replay.
__global__ __launch_bounds__(SCAN_B) void p45_offsets(int N, int nb) {
    __shared__ int wsum[16];
    __shared__ int sc[SCAN_B];
    int tid = threadIdx.x;
    int lane = tid & 31;
    int wid = tid >> 5;
    int b = blockIdx.x;
    int v = (tid < nb) ? g_bsums[tid] : 0;
    int s = v;
#pragma unroll
    for (int off = 1; off < 32; off <<= 1) {
        int t = __shfl_up_sync(0xffffffffu, s, off);
        if (lane >= off) s += t;
    }
    if (lane == 31) wsum[wid] = s;
    __syncthreads();
    if (wid == 0 && lane < 16) {
        int w = wsum[lane];
#pragma unroll
        for (int off = 1; off < 16; off <<= 1) {
            int t = __shfl_up_sync(0x0000ffffu, w, off);
            if (lane >= off) w += t;
        }
        wsum[lane] = w;
    }
    __syncthreads();
    sc[tid] = s + ((wid > 0) ? wsum[wid - 1] : 0);
    __syncthreads();
    int offset = (b > 0) ? sc[b - 1] : 0;
    int i = b * SCAN_B + tid;
    if (i < N) {
        int val = g_base[i] + offset;
        g_base[i] = val;
        g_cursor[i] = val;
        g_cnt[i] = 0;                 // dead after p3; pre-zero for next replay
    }
}

// P6: bucket dst indices into CSR order
__global__ void p6_bucket(const int* __restrict__ ei, int E) {
    int e = blockIdx.x * blockDim.x + threadIdx.x;
    if (e < E) {
        int src = ei[e];
        int dst = ei[E + e];
        int pos = atomicAdd(&g_cursor[src], 1);
        g_sorted[pos] = dst;
    }
}

// ---------------------------------------------------------------------------
// P7: gather-aggregate. One warp per node, 4-way unrolled gather, fused
// normalization AND bf16 hi/lo split (removes split work from the GEMM).
// Runs standalone at high occupancy (round-10 lesson: do not fuse).
// ---------------------------------------------------------------------------
__global__ __launch_bounds__(256) void p7_gather(
        const float* __restrict__ x, int N, int E) {
    int n = (blockIdx.x * 256 + threadIdx.x) >> 5;
    int lane = threadIdx.x & 31;
    if (n >= N) return;
    int s = g_base[n];
    int eend = (n + 1 < N) ? g_base[n + 1] : E;
    int cnt = eend - s;
    const float4* x4 = reinterpret_cast<const float4*>(x);
    const int* sp = g_sorted + s;
    float4 acc = make_float4(0.f, 0.f, 0.f, 0.f);
    for (int b = 0; b < cnt; b += 32) {
        int dv = (b + lane < cnt) ? sp[b + lane] : 0;
        int m = min(32, cnt - b);
        int j = 0;
        for (; j + 4 <= m; j += 4) {
            int d0 = __shfl_sync(0xffffffffu, dv, j);
            int d1 = __shfl_sync(0xffffffffu, dv, j + 1);
            int d2 = __shfl_sync(0xffffffffu, dv, j + 2);
            int d3 = __shfl_sync(0xffffffffu, dv, j + 3);
            float4 v0 = x4[(size_t)d0 * 32 + lane];
            float4 v1 = x4[(size_t)d1 * 32 + lane];
            float4 v2 = x4[(size_t)d2 * 32 + lane];
            float4 v3 = x4[(size_t)d3 * 32 + lane];
            acc.x += v0.x; acc.y += v0.y; acc.z += v0.z; acc.w += v0.w;
            acc.x += v1.x; acc.y += v1.y; acc.z += v1.z; acc.w += v1.w;
            acc.x += v2.x; acc.y += v2.y; acc.z += v2.z; acc.w += v2.w;
            acc.x += v3.x; acc.y += v3.y; acc.z += v3.z; acc.w += v3.w;
        }
        for (; j < m; j++) {
            int d = __shfl_sync(0xffffffffu, dv, j);
            float4 v = x4[(size_t)d * 32 + lane];
            acc.x += v.x; acc.y += v.y; acc.z += v.z; acc.w += v.w;
        }
    }
    float rd = (cnt > 0) ? (1.0f / (float)cnt) : 1.0f;
    acc.x *= rd; acc.y *= rd; acc.z *= rd; acc.w *= rd;
    // bf16x3 split in-register, write hi/lo planes (8B per plane per lane)
    __nv_bfloat16 hx = __float2bfloat16(acc.x), hy = __float2bfloat16(acc.y);
    __nv_bfloat16 hz = __float2bfloat16(acc.z), hw = __float2bfloat16(acc.w);
    __nv_bfloat162 hp0 = __halves2bfloat162(hx, hy);
    __nv_bfloat162 hp1 = __halves2bfloat162(hz, hw);
    __nv_bfloat162 lp0 = __halves2bfloat162(
        __float2bfloat16(acc.x - __bfloat162float(hx)),
        __float2bfloat16(acc.y - __bfloat162float(hy)));
    __nv_bfloat162 lp1 = __halves2bfloat162(
        __float2bfloat16(acc.z - __bfloat162float(hz)),
        __float2bfloat16(acc.w - __bfloat162float(hw)));
    size_t o2 = (size_t)n * 32 + lane;
    reinterpret_cast<uint2*>(g_ahi)[o2] =
        make_uint2(*(uint32_t*)&hp0, *(uint32_t*)&hp1);
    reinterpret_cast<uint2*>(g_alo)[o2] =
        make_uint2(*(uint32_t*)&lp0, *(uint32_t*)&lp1);
}

// ---------------------------------------------------------------------------
// K2: PERSISTENT fused GEMM  out = agg @ W^T + x @ B^T  (bf16x3 mma.sync).
// Static strided tiles (uniform cost -> no ticket). Weights staged once per
// CTA. agg staged as pure uint4 copies of pre-split planes; x via register
// prefetch + in-register split.
// ---------------------------------------------------------------------------
__device__ __forceinline__ void bsplit(float v, __nv_bfloat16* hi, __nv_bfloat16* lo) {
    __nv_bfloat16 h = __float2bfloat16(v);
    *hi = h;
    *lo = __float2bfloat16(v - __bfloat162float(h));
}

#define MMA_BF16(d, a, b)                                                     \
    asm volatile("mma.sync.aligned.m16n8k16.row.col.f32.bf16.bf16.f32 "       \
                 "{%0,%1,%2,%3}, {%4,%5,%6,%7}, {%8,%9}, {%0,%1,%2,%3};"      \
                 : "+f"((d)[0]), "+f"((d)[1]), "+f"((d)[2]), "+f"((d)[3])     \
                 : "r"((a)[0]), "r"((a)[1]), "r"((a)[2]), "r"((a)[3]),        \
                   "r"((b)[0]), "r"((b)[1]))

__device__ __forceinline__ void mma_phase(
        const __nv_bfloat16* __restrict__ wh, const __nv_bfloat16* __restrict__ wl,
        const __nv_bfloat16* __restrict__ sAhi, const __nv_bfloat16* __restrict__ sAlo,
        int wm, int wn, int g, int tg, float (&acc)[2][8][4]) {
#pragma unroll
    for (int ks = 0; ks < 8; ks++) {
        const int kc = ks * 16 + tg * 2;
        uint32_t bhi[8][2], blo[8][2];
#pragma unroll
        for (int nt = 0; nt < 8; nt++) {
            int j0 = wn * 64 + nt * 8 + g;
            const __nv_bfloat16* p = wh + j0 * SSTRIDE + kc;
            bhi[nt][0] = *reinterpret_cast<const uint32_t*>(p);
            bhi[nt][1] = *reinterpret_cast<const uint32_t*>(p + 8);
            const __nv_bfloat16* q = wl + j0 * SSTRIDE + kc;
            blo[nt][0] = *reinterpret_cast<const uint32_t*>(q);
            blo[nt][1] = *reinterpret_cast<const uint32_t*>(q + 8);
        }
#pragma unroll
        for (int mt = 0; mt < 2; mt++) {
            int r0 = wm * 32 + mt * 16 + g;
            uint32_t ahi[4], alo[4];
            const __nv_bfloat16* p0 = sAhi + r0 * SSTRIDE + kc;
            const __nv_bfloat16* p1 = sAhi + (r0 + 8) * SSTRIDE + kc;
            ahi[0] = *reinterpret_cast<const uint32_t*>(p0);
            ahi[1] = *reinterpret_cast<const uint32_t*>(p1);
            ahi[2] = *reinterpret_cast<const uint32_t*>(p0 + 8);
            ahi[3] = *reinterpret_cast<const uint32_t*>(p1 + 8);
            const __nv_bfloat16* q0 = sAlo + r0 * SSTRIDE + kc;
            const __nv_bfloat16* q1 = sAlo + (r0 + 8) * SSTRIDE + kc;
            alo[0] = *reinterpret_cast<const uint32_t*>(q0);
            alo[1] = *reinterpret_cast<const uint32_t*>(q1);
            alo[2] = *reinterpret_cast<const uint32_t*>(q0 + 8);
            alo[3] = *reinterpret_cast<const uint32_t*>(q1 + 8);
#pragma unroll
            for (int nt = 0; nt < 8; nt++) {
                MMA_BF16(acc[mt][nt], ahi, bhi[nt]);
                MMA_BF16(acc[mt][nt], ahi, blo[nt]);
                MMA_BF16(acc[mt][nt], alo, bhi[nt]);
            }
        }
    }
}

__global__ __launch_bounds__(256, 1) void gemm_persist(
        const float* __restrict__ x, float* __restrict__ out,
        int N, int ntiles) {
    extern __shared__ __nv_bfloat16 smem[];
    __nv_bfloat16* sWhi = smem;
    __nv_bfloat16* sWlo = sWhi + 128 * SSTRIDE;
    __nv_bfloat16* sBhi = sWlo + 128 * SSTRIDE;
    __nv_bfloat16* sBlo = sBhi + 128 * SSTRIDE;
    __nv_bfloat16* sAhi = sBlo + 128 * SSTRIDE;   // A tile (reused per phase)
    __nv_bfloat16* sAlo = sAhi + 128 * SSTRIDE;

    const int tid = threadIdx.x;
    const int lane = tid & 31;
    const int warp = tid >> 5;
    const int wm = warp & 3;
    const int wn = warp >> 2;
    const int g = lane >> 2;
    const int tg = lane & 3;
    const float4* x4 = reinterpret_cast<const float4*>(x);
    const uint4* ahi4 = reinterpret_cast<const uint4*>(g_ahi);
    const uint4* alo4 = reinterpret_cast<const uint4*>(g_alo);

    // Stage all 4 weight planes ONCE per CTA.
#pragma unroll 4
    for (int i = tid; i < 128 * 16; i += 256) {
        int r = i >> 4;
        int c8 = (i & 15) << 3;
        *reinterpret_cast<uint4*>(sWhi + r * SSTRIDE + c8) =
            reinterpret_cast<const uint4*>(g_whi)[i];
        *reinterpret_cast<uint4*>(sWlo + r * SSTRIDE + c8) =
            reinterpret_cast<const uint4*>(g_wlo)[i];
        *reinterpret_cast<uint4*>(sBhi + r * SSTRIDE + c8) =
            reinterpret_cast<const uint4*>(g_bhi)[i];
        *reinterpret_cast<uint4*>(sBlo + r * SSTRIDE + c8) =
            reinterpret_cast<const uint4*>(g_blo)[i];
    }

    for (int tile = blockIdx.x; tile < ntiles; tile += gridDim.x) {
        int rowBase = tile * GTILE;
        __syncthreads();   // prior tile's fragment reads done before restage

        float acc[2][8][4];
#pragma unroll
        for (int a = 0; a < 2; a++)
#pragma unroll
            for (int b = 0; b < 8; b++)
#pragma unroll
                for (int c = 0; c < 4; c++) acc[a][b][c] = 0.f;

        // ---- stage agg planes: pure uint4 copies (split done in p7) ----
        const uint4 z4 = make_uint4(0u, 0u, 0u, 0u);
#pragma unroll
        for (int j = 0; j < 8; j++) {
            int i = tid + j * 256;              // [0, 2048): 128 rows x 16 uint4
            int r = i >> 4;
            int c8 = (i & 15) << 3;
            int gr = rowBase + r;
            bool ok = (gr < N);
            size_t gi = (size_t)gr * 16 + (i & 15);
            uint4 h = ok ? ahi4[gi] : z4;
            uint4 l = ok ? alo4[gi] : z4;
            *reinterpret_cast<uint4*>(sAhi + r * SSTRIDE + c8) = h;
            *reinterpret_cast<uint4*>(sAlo + r * SSTRIDE + c8) = l;
        }
        // ---- prefetch x tile into registers (hides under phase-0 MMA) ----
        float4 xr[16];
#pragma unroll
        for (int j = 0; j < 16; j++) {
            int i = tid + j * 256;
            int gr = rowBase + (i >> 5);
            xr[j] = (gr < N) ? x4[(size_t)gr * 32 + (i & 31)]
                             : make_float4(0.f, 0.f, 0.f, 0.f);
        }
        __syncthreads();

        mma_phase(sWhi, sWlo, sAhi, sAlo, wm, wn, g, tg, acc);   // phase 0

        __syncthreads();   // phase-0 fragment reads done before restage
#pragma unroll
        for (int j = 0; j < 16; j++) {
            int i = tid + j * 256;
            int o = (i >> 5) * SSTRIDE + ((i & 31) << 2);
            bsplit(xr[j].x, sAhi + o, sAlo + o);
            bsplit(xr[j].y, sAhi + o + 1, sAlo + o + 1);
            bsplit(xr[j].z, sAhi + o + 2, sAlo + o + 2);
            bsplit(xr[j].w, sAhi + o + 3, sAlo + o + 3);
        }
        __syncthreads();

        mma_phase(sBhi, sBlo, sAhi, sAlo, wm, wn, g, tg, acc);   // phase 1

        // Epilogue
#pragma unroll
        for (int mt = 0; mt < 2; mt++) {
            int r = rowBase + wm * 32 + mt * 16 + g;
#pragma unroll
            for (int nt = 0; nt < 8; nt++) {
                int c = wn * 64 + nt * 8 + tg * 2;
                if (r < N) {
                    float2 v = make_float2(acc[mt][nt][0], acc[mt][nt][1]);
                    *reinterpret_cast<float2*>(out + (size_t)r * F + c) = v;
                }
                if (r + 8 < N) {
                    float2 v = make_float2(acc[mt][nt][2], acc[mt][nt][3]);
                    *reinterpret_cast<float2*>(out + (size_t)(r + 8) * F + c) = v;
                }
            }
        }
    }
}

// ---------------------------------------------------------------------------
extern "C" void kernel_launch(void* const* d_in, const int* in_sizes, int n_in,
                              void* d_out, int out_size) {
    const float* x = (const float*)d_in[0];
    const int* ei = (const int*)d_in[1];     // int32 (JAX x64-disabled)
    const float* W = (const float*)d_in[2];
    const float* B = (const float*)d_in[3];
    float* out = (float*)d_out;

    int N = in_sizes[0] / F;   // 100000
    int E = in_sizes[1] / 2;   // 625000
    if (N > MAX_NODES) N = MAX_NODES;
    if (E > MAX_EDGES) E = MAX_EDGES;

    int nb = (N + SCAN_B - 1) / SCAN_B;      // scan blocks (196)

    p1_conv<<<(F * F) / 256, 256>>>(W, B);
    p2_hist<<<(E + 255) / 256, 256>>>(ei, E);
    p3_scan<<<nb, SCAN_B>>>(N);
    p45_offsets<<<nb, SCAN_B>>>(N, nb);
    p6_bucket<<<(E + 255) / 256, 256>>>(ei, E);
    p7_gather<<<(N * 32 + 255) / 256, 256>>>(x, N, E);

    // smem: 6 planes * 128 rows * SSTRIDE bf16 = 208896 B
    size_t smem = (size_t)6 * 128 * SSTRIDE * sizeof(__nv_bfloat16);
    cudaFuncSetAttribute(gemm_persist, cudaFuncAttributeMaxDynamicSharedMemorySize,
                         (int)smem);
    int ntiles = (N + GTILE - 1) / GTILE;
    gemm_persist<<<152, 256, smem>>>(x, out, N, ntiles);
}

// round 15
// speedup vs baseline: 1.0617x; 1.0142x over previous
#include <cuda_runtime.h>
#include <cuda_bf16.h>
#include <cstdint>

#define MAX_NODES 100000
#define MAX_EDGES 625000
#define F 128
#define SSTRIDE 136   // padded bf16 row stride -> conflict-free frags/ldmatrix
#define SCAN_B 512    // nodes per scan block
#define GTILE 128     // rows per tile

__device__ int g_cnt[MAX_NODES];        // zero-init at load; re-zeroed by p45
__device__ int g_base[MAX_NODES];
__device__ int g_cursor[MAX_NODES];
__device__ int g_sorted[MAX_EDGES];
__device__ int g_bsums[256];
// aggregated features, pre-split bf16 hi/lo planes (written by p7)
__device__ __align__(16) __nv_bfloat16 g_ahi[(size_t)MAX_NODES * F];
__device__ __align__(16) __nv_bfloat16 g_alo[(size_t)MAX_NODES * F];
// pre-split weight planes (hi/lo bf16), filled once per launch
__device__ __align__(16) __nv_bfloat16 g_whi[F * F];
__device__ __align__(16) __nv_bfloat16 g_wlo[F * F];
__device__ __align__(16) __nv_bfloat16 g_bhi[F * F];
__device__ __align__(16) __nv_bfloat16 g_blo[F * F];

// ---------------------------------------------------------------------------
// P1: pre-split W/B into bf16 hi/lo planes
// ---------------------------------------------------------------------------
__global__ void p1_conv(const float* __restrict__ W, const float* __restrict__ B) {
    int i = blockIdx.x * blockDim.x + threadIdx.x;
    float w = W[i];
    __nv_bfloat16 h = __float2bfloat16(w);
    g_whi[i] = h;
    g_wlo[i] = __float2bfloat16(w - __bfloat162float(h));
    float b = B[i];
    h = __float2bfloat16(b);
    g_bhi[i] = h;
    g_blo[i] = __float2bfloat16(b - __bfloat162float(h));
}

// P2: histogram of src
__global__ void p2_hist(const int* __restrict__ ei, int E) {
    int e = blockIdx.x * blockDim.x + threadIdx.x;
    if (e < E) atomicAdd(&g_cnt[ei[e]], 1);
}

// P3: per-block exclusive scan via warp shuffles (512 threads, 16 warps)
__global__ __launch_bounds__(SCAN_B) void p3_scan(int N) {
    __shared__ int wsum[16];
    int tid = threadIdx.x;
    int lane = tid & 31;
    int wid = tid >> 5;
    int i = blockIdx.x * SCAN_B + tid;
    int v = (i < N) ? g_cnt[i] : 0;
    int s = v;
#pragma unroll
    for (int off = 1; off < 32; off <<= 1) {
        int t = __shfl_up_sync(0xffffffffu, s, off);
        if (lane >= off) s += t;
    }
    if (lane == 31) wsum[wid] = s;
    __syncthreads();
    if (wid == 0 && lane < 16) {
        int w = wsum[lane];
#pragma unroll
        for (int off = 1; off < 16; off <<= 1) {
            int t = __shfl_up_sync(0x0000ffffu, w, off);
            if (lane >= off) w += t;
        }
        wsum[lane] = w;
    }
    __syncthreads();
    int incl = s + ((wid > 0) ? wsum[wid - 1] : 0);
    if (i < N) g_base[i] = incl - v;            // exclusive within block
    if (tid == SCAN_B - 1) g_bsums[blockIdx.x] = incl;
}

// P45: redundant block-sum scan per block, apply offset, seed cursors,
// re-zero g_cnt for next replay.
__global__ __launch_bounds__(SCAN_B) void p45_offsets(int N, int nb) {
    __shared__ int wsum[16];
    __shared__ int sc[SCAN_B];
    int tid = threadIdx.x;
    int lane = tid & 31;
    int wid = tid >> 5;
    int b = blockIdx.x;
    int v = (tid < nb) ? g_bsums[tid] : 0;
    int s = v;
#pragma unroll
    for (int off = 1; off < 32; off <<= 1) {
        int t = __shfl_up_sync(0xffffffffu, s, off);
        if (lane >= off) s += t;
    }
    if (lane == 31) wsum[wid] = s;
    __syncthreads();
    if (wid == 0 && lane < 16) {
        int w = wsum[lane];
#pragma unroll
        for (int off = 1; off < 16; off <<= 1) {
            int t = __shfl_up_sync(0x0000ffffu, w, off);
            if (lane >= off) w += t;
        }
        wsum[lane] = w;
    }
    __syncthreads();
    sc[tid] = s + ((wid > 0) ? wsum[wid - 1] : 0);
    __syncthreads();
    int offset = (b > 0) ? sc[b - 1] : 0;
    int i = b * SCAN_B + tid;
    if (i < N) {
        int val = g_base[i] + offset;
        g_base[i] = val;
        g_cursor[i] = val;
        g_cnt[i] = 0;                 // dead after p3; pre-zero for next replay
    }
}

// P6: bucket dst indices into CSR order
__global__ void p6_bucket(const int* __restrict__ ei, int E) {
    int e = blockIdx.x * blockDim.x + threadIdx.x;
    if (e < E) {
        int src = ei[e];
        int dst = ei[E + e];
        int pos = atomicAdd(&g_cursor[src], 1);
        g_sorted[pos] = dst;
    }
}

// ---------------------------------------------------------------------------
// P7: gather-aggregate. One warp per node, 4-way unrolled gather, fused
// normalization AND bf16 hi/lo split. Standalone at high occupancy.
// ---------------------------------------------------------------------------
__global__ __launch_bounds__(256) void p7_gather(
        const float* __restrict__ x, int N, int E) {
    int n = (blockIdx.x * 256 + threadIdx.x) >> 5;
    int lane = threadIdx.x & 31;
    if (n >= N) return;
    int s = g_base[n];
    int eend = (n + 1 < N) ? g_base[n + 1] : E;
    int cnt = eend - s;
    const float4* x4 = reinterpret_cast<const float4*>(x);
    const int* sp = g_sorted + s;
    float4 acc = make_float4(0.f, 0.f, 0.f, 0.f);
    for (int b = 0; b < cnt; b += 32) {
        int dv = (b + lane < cnt) ? sp[b + lane] : 0;
        int m = min(32, cnt - b);
        int j = 0;
        for (; j + 4 <= m; j += 4) {
            int d0 = __shfl_sync(0xffffffffu, dv, j);
            int d1 = __shfl_sync(0xffffffffu, dv, j + 1);
            int d2 = __shfl_sync(0xffffffffu, dv, j + 2);
            int d3 = __shfl_sync(0xffffffffu, dv, j + 3);
            float4 v0 = x4[(size_t)d0 * 32 + lane];
            float4 v1 = x4[(size_t)d1 * 32 + lane];
            float4 v2 = x4[(size_t)d2 * 32 + lane];
            float4 v3 = x4[(size_t)d3 * 32 + lane];
            acc.x += v0.x; acc.y += v0.y; acc.z += v0.z; acc.w += v0.w;
            acc.x += v1.x; acc.y += v1.y; acc.z += v1.z; acc.w += v1.w;
            acc.x += v2.x; acc.y += v2.y; acc.z += v2.z; acc.w += v2.w;
            acc.x += v3.x; acc.y += v3.y; acc.z += v3.z; acc.w += v3.w;
        }
        for (; j < m; j++) {
            int d = __shfl_sync(0xffffffffu, dv, j);
            float4 v = x4[(size_t)d * 32 + lane];
            acc.x += v.x; acc.y += v.y; acc.z += v.z; acc.w += v.w;
        }
    }
    float rd = (cnt > 0) ? (1.0f / (float)cnt) : 1.0f;
    acc.x *= rd; acc.y *= rd; acc.z *= rd; acc.w *= rd;
    __nv_bfloat16 hx = __float2bfloat16(acc.x), hy = __float2bfloat16(acc.y);
    __nv_bfloat16 hz = __float2bfloat16(acc.z), hw = __float2bfloat16(acc.w);
    __nv_bfloat162 hp0 = __halves2bfloat162(hx, hy);
    __nv_bfloat162 hp1 = __halves2bfloat162(hz, hw);
    __nv_bfloat162 lp0 = __halves2bfloat162(
        __float2bfloat16(acc.x - __bfloat162float(hx)),
        __float2bfloat16(acc.y - __bfloat162float(hy)));
    __nv_bfloat162 lp1 = __halves2bfloat162(
        __float2bfloat16(acc.z - __bfloat162float(hz)),
        __float2bfloat16(acc.w - __bfloat162float(hw)));
    size_t o2 = (size_t)n * 32 + lane;
    reinterpret_cast<uint2*>(g_ahi)[o2] =
        make_uint2(*(uint32_t*)&hp0, *(uint32_t*)&hp1);
    reinterpret_cast<uint2*>(g_alo)[o2] =
        make_uint2(*(uint32_t*)&lp0, *(uint32_t*)&lp1);
}

// ---------------------------------------------------------------------------
// K2: PERSISTENT fused GEMM  out = agg @ W^T + x @ B^T  (bf16x3 mma.sync).
// Fragment loads via ldmatrix.x4 (4x fewer shared-load instructions).
// ---------------------------------------------------------------------------
__device__ __forceinline__ void bsplit(float v, __nv_bfloat16* hi, __nv_bfloat16* lo) {
    __nv_bfloat16 h = __float2bfloat16(v);
    *hi = h;
    *lo = __float2bfloat16(v - __bfloat162float(h));
}

#define MMA_BF16(d, a, b)                                                     \
    asm volatile("mma.sync.aligned.m16n8k16.row.col.f32.bf16.bf16.f32 "       \
                 "{%0,%1,%2,%3}, {%4,%5,%6,%7}, {%8,%9}, {%0,%1,%2,%3};"      \
                 : "+f"((d)[0]), "+f"((d)[1]), "+f"((d)[2]), "+f"((d)[3])     \
                 : "r"((a)[0]), "r"((a)[1]), "r"((a)[2]), "r"((a)[3]),        \
                   "r"((b)[0]), "r"((b)[1]))

#define LDSM4(r0, r1, r2, r3, addr)                                           \
    asm volatile("ldmatrix.sync.aligned.m8n8.x4.shared.b16 {%0,%1,%2,%3}, [%4];" \
                 : "=r"(r0), "=r"(r1), "=r"(r2), "=r"(r3) : "r"(addr))

// aAddr/bAddr: per-lane byte addresses (hi planes); lo plane at +PLANE_OFF.
// aAddr row = wm*32 + (lane&15), col = (lane>>4)*8   [A frag m16k16]
// bAddr row = wn*64 + (lane&7) + ((lane&16)?8:0), col = (lane&8)?8:0  [B n16k16 pair]
#define MT_OFF (16 * SSTRIDE * 2)    // +16 rows in bytes
#define PR_OFF (16 * SSTRIDE * 2)    // +16 n-rows in bytes

__device__ __forceinline__ void mma_phase_ldsm(
        uint32_t aHi, uint32_t aLo, uint32_t bHi, uint32_t bLo,
        float (&acc)[2][8][4]) {
#pragma unroll
    for (int ks = 0; ks < 8; ks++) {
        const uint32_t ko = ks * 32;        // 16 bf16 cols = 32 bytes
        uint32_t ahi[2][4], alo[2][4];
        uint32_t bhi[8][2], blo[8][2];
        LDSM4(ahi[0][0], ahi[0][1], ahi[0][2], ahi[0][3], aHi + ko);
        LDSM4(ahi[1][0], ahi[1][1], ahi[1][2], ahi[1][3], aHi + ko + MT_OFF);
        LDSM4(alo[0][0], alo[0][1], alo[0][2], alo[0][3], aLo + ko);
        LDSM4(alo[1][0], alo[1][1], alo[1][2], alo[1][3], aLo + ko + MT_OFF);
#pragma unroll
        for (int p = 0; p < 4; p++) {
            LDSM4(bhi[2 * p][0], bhi[2 * p][1], bhi[2 * p + 1][0], bhi[2 * p + 1][1],
                  bHi + ko + p * PR_OFF);
            LDSM4(blo[2 * p][0], blo[2 * p][1], blo[2 * p + 1][0], blo[2 * p + 1][1],
                  bLo + ko + p * PR_OFF);
        }
#pragma unroll
        for (int mt = 0; mt < 2; mt++)
#pragma unroll
            for (int nt = 0; nt < 8; nt++) {
                MMA_BF16(acc[mt][nt], ahi[mt], bhi[nt]);
                MMA_BF16(acc[mt][nt], ahi[mt], blo[nt]);
                MMA_BF16(acc[mt][nt], alo[mt], bhi[nt]);
            }
    }
}

__global__ __launch_bounds__(256, 1) void gemm_persist(
        const float* __restrict__ x, float* __restrict__ out,
        int N, int ntiles) {
    extern __shared__ __nv_bfloat16 smem[];
    __nv_bfloat16* sWhi = smem;
    __nv_bfloat16* sWlo = sWhi + 128 * SSTRIDE;
    __nv_bfloat16* sBhi = sWlo + 128 * SSTRIDE;
    __nv_bfloat16* sBlo = sBhi + 128 * SSTRIDE;
    __nv_bfloat16* sAhi = sBlo + 128 * SSTRIDE;   // A tile (reused per phase)
    __nv_bfloat16* sAlo = sAhi + 128 * SSTRIDE;

    const int tid = threadIdx.x;
    const int lane = tid & 31;
    const int warp = tid >> 5;
    const int wm = warp & 3;
    const int wn = warp >> 2;
    const int g = lane >> 2;
    const int tg = lane & 3;
    const float4* x4 = reinterpret_cast<const float4*>(x);
    const uint4* ahi4 = reinterpret_cast<const uint4*>(g_ahi);
    const uint4* alo4 = reinterpret_cast<const uint4*>(g_alo);

    // per-lane ldmatrix addresses (byte offsets in shared space)
    const int aRow = wm * 32 + (lane & 15);
    const int aCol = (lane >> 4) << 3;
    const int bRow = wn * 64 + (lane & 7) + ((lane & 16) ? 8 : 0);
    const int bCol = (lane & 8) ? 8 : 0;
    const uint32_t aHiAddr = (uint32_t)__cvta_generic_to_shared(sAhi) +
                             (uint32_t)(aRow * SSTRIDE + aCol) * 2u;
    const uint32_t aLoAddr = (uint32_t)__cvta_generic_to_shared(sAlo) +
                             (uint32_t)(aRow * SSTRIDE + aCol) * 2u;
    const uint32_t wHiAddr = (uint32_t)__cvta_generic_to_shared(sWhi) +
                             (uint32_t)(bRow * SSTRIDE + bCol) * 2u;
    const uint32_t wLoAddr = (uint32_t)__cvta_generic_to_shared(sWlo) +
                             (uint32_t)(bRow * SSTRIDE + bCol) * 2u;
    const uint32_t bHiAddr = (uint32_t)__cvta_generic_to_shared(sBhi) +
                             (uint32_t)(bRow * SSTRIDE + bCol) * 2u;
    const uint32_t bLoAddr = (uint32_t)__cvta_generic_to_shared(sBlo) +
                             (uint32_t)(bRow * SSTRIDE + bCol) * 2u;

    // Stage all 4 weight planes ONCE per CTA.
#pragma unroll 4
    for (int i = tid; i < 128 * 16; i += 256) {
        int r = i >> 4;
        int c8 = (i & 15) << 3;
        *reinterpret_cast<uint4*>(sWhi + r * SSTRIDE + c8) =
            reinterpret_cast<const uint4*>(g_whi)[i];
        *reinterpret_cast<uint4*>(sWlo + r * SSTRIDE + c8) =
            reinterpret_cast<const uint4*>(g_wlo)[i];
        *reinterpret_cast<uint4*>(sBhi + r * SSTRIDE + c8) =
            reinterpret_cast<const uint4*>(g_bhi)[i];
        *reinterpret_cast<uint4*>(sBlo + r * SSTRIDE + c8) =
            reinterpret_cast<const uint4*>(g_blo)[i];
    }

    for (int tile = blockIdx.x; tile < ntiles; tile += gridDim.x) {
        int rowBase = tile * GTILE;
        __syncthreads();   // prior tile's fragment reads done before restage

        float acc[2][8][4];
#pragma unroll
        for (int a = 0; a < 2; a++)
#pragma unroll
            for (int b = 0; b < 8; b++)
#pragma unroll
                for (int c = 0; c < 4; c++) acc[a][b][c] = 0.f;

        // ---- stage agg planes: pure uint4 copies (split done in p7) ----
        const uint4 z4 = make_uint4(0u, 0u, 0u, 0u);
#pragma unroll
        for (int j = 0; j < 8; j++) {
            int i = tid + j * 256;              // [0, 2048): 128 rows x 16 uint4
            int r = i >> 4;
            int c8 = (i & 15) << 3;
            int gr = rowBase + r;
            bool ok = (gr < N);
            size_t gi = (size_t)gr * 16 + (i & 15);
            uint4 h = ok ? ahi4[gi] : z4;
            uint4 l = ok ? alo4[gi] : z4;
            *reinterpret_cast<uint4*>(sAhi + r * SSTRIDE + c8) = h;
            *reinterpret_cast<uint4*>(sAlo + r * SSTRIDE + c8) = l;
        }
        // ---- prefetch x tile into registers (hides under phase-0 MMA) ----
        float4 xr[16];
#pragma unroll
        for (int j = 0; j < 16; j++) {
            int i = tid + j * 256;
            int gr = rowBase + (i >> 5);
            xr[j] = (gr < N) ? x4[(size_t)gr * 32 + (i & 31)]
                             : make_float4(0.f, 0.f, 0.f, 0.f);
        }
        __syncthreads();

        mma_phase_ldsm(aHiAddr, aLoAddr, wHiAddr, wLoAddr, acc);   // phase 0

        __syncthreads();   // phase-0 fragment reads done before restage
#pragma unroll
        for (int j = 0; j < 16; j++) {
            int i = tid + j * 256;
            int o = (i >> 5) * SSTRIDE + ((i & 31) << 2);
            bsplit(xr[j].x, sAhi + o, sAlo + o);
            bsplit(xr[j].y, sAhi + o + 1, sAlo + o + 1);
            bsplit(xr[j].z, sAhi + o + 2, sAlo + o + 2);
            bsplit(xr[j].w, sAhi + o + 3, sAlo + o + 3);
        }
        __syncthreads();

        mma_phase_ldsm(aHiAddr, aLoAddr, bHiAddr, bLoAddr, acc);   // phase 1

        // Epilogue
#pragma unroll
        for (int mt = 0; mt < 2; mt++) {
            int r = rowBase + wm * 32 + mt * 16 + g;
#pragma unroll
            for (int nt = 0; nt < 8; nt++) {
                int c = wn * 64 + nt * 8 + tg * 2;
                if (r < N) {
                    float2 v = make_float2(acc[mt][nt][0], acc[mt][nt][1]);
                    *reinterpret_cast<float2*>(out + (size_t)r * F + c) = v;
                }
                if (r + 8 < N) {
                    float2 v = make_float2(acc[mt][nt][2], acc[mt][nt][3]);
                    *reinterpret_cast<float2*>(out + (size_t)(r + 8) * F + c) = v;
                }
            }
        }
    }
}

// ---------------------------------------------------------------------------
extern "C" void kernel_launch(void* const* d_in, const int* in_sizes, int n_in,
                              void* d_out, int out_size) {
    const float* x = (const float*)d_in[0];
    const int* ei = (const int*)d_in[1];     // int32 (JAX x64-disabled)
    const float* W = (const float*)d_in[2];
    const float* B = (const float*)d_in[3];
    float* out = (float*)d_out;

    int N = in_sizes[0] / F;   // 100000
    int E = in_sizes[1] / 2;   // 625000
    if (N > MAX_NODES) N = MAX_NODES;
    if (E > MAX_EDGES) E = MAX_EDGES;

    int nb = (N + SCAN_B - 1) / SCAN_B;      // scan blocks (196)

    p1_conv<<<(F * F) / 256, 256>>>(W, B);
    p2_hist<<<(E + 255) / 256, 256>>>(ei, E);
    p3_scan<<<nb, SCAN_B>>>(N);
    p45_offsets<<<nb, SCAN_B>>>(N, nb);
    p6_bucket<<<(E + 255) / 256, 256>>>(ei, E);
    p7_gather<<<(N * 32 + 255) / 256, 256>>>(x, N, E);

    // smem: 6 planes * 128 rows * SSTRIDE bf16 = 208896 B
    size_t smem = (size_t)6 * 128 * SSTRIDE * sizeof(__nv_bfloat16);
    cudaFuncSetAttribute(gemm_persist, cudaFuncAttributeMaxDynamicSharedMemorySize,
                         (int)smem);
    int ntiles = (N + GTILE - 1) / GTILE;
    gemm_persist<<<152, 256, smem>>>(x, out, N, ntiles);
}